// round 1
// baseline (speedup 1.0000x reference)
#include <cuda_runtime.h>
#include <math.h>

// Problem constants (fixed by the dataset)
#define Nn 50000
#define Ee 800000
#define Dd 32
#define NL 6
#define KK 160          // GEMM K: 32 (h) + 128 (feats)
#define CN 96           // GEMM N: 3 groups of 32 (base, *scale, *inv_scale)
#define SCAN_BLOCKS 196 // ceil(Nn/256)

// ---------------- device scratch (no allocations allowed) ----------------
__device__ float g_h0[Nn * Dd];
__device__ float g_h1[Nn * Dd];
__device__ float g_X[Nn * KK];           // per-node GEMM input rows
__device__ float g_Wc[NL * KK * CN];     // expanded lin_W per layer
__device__ float g_scale[Nn];
__device__ float g_deg[Nn];
__device__ int   g_indeg[Nn];
__device__ int   g_start[Nn];
__device__ int   g_cursor[Nn];
__device__ int   g_edges[Ee];
__device__ float g_rel[NL * Dd];
__device__ float g_sum;
__device__ int   g_pred[Nn];
__device__ int   g_bsum[256];

__device__ __forceinline__ float* hbuf(int s) { return s ? g_h1 : g_h0; }

// ---------------- init: boundary layer input, degree, counters ----------------
__global__ void k_init(const int* __restrict__ hptr) {
    int idx = blockIdx.x * blockDim.x + threadIdx.x;
    if (idx >= Nn * Dd) return;
    int n = idx >> 5;
    int h = *hptr;
    g_h0[idx] = (n == h) ? 0.0f : 100.0f;
    if ((idx & 31) == 0) {
        g_deg[n] = 1.0f;   // degree_out starts at +1
        g_indeg[n] = 0;
    }
    if (idx == 0) g_sum = 0.0f;
}

// ---------------- edge counting ----------------
__global__ void k_count(const int* __restrict__ node_out, const float* __restrict__ ew) {
    int e = blockIdx.x * blockDim.x + threadIdx.x;
    if (e >= Ee) return;
    int o = node_out[e];
    atomicAdd(&g_deg[o], ew[e]);
    atomicAdd(&g_indeg[o], 1);
}

// ---------------- 3-phase exclusive scan over g_indeg ----------------
__global__ void k_scan1() {
    __shared__ int sh[256];
    int i = blockIdx.x * 256 + threadIdx.x;
    int t = threadIdx.x;
    int v = (i < Nn) ? g_indeg[i] : 0;
    sh[t] = v; __syncthreads();
    for (int off = 1; off < 256; off <<= 1) {
        int u = (t >= off) ? sh[t - off] : 0;
        __syncthreads();
        sh[t] += u;
        __syncthreads();
    }
    if (i < Nn) g_start[i] = sh[t] - v;   // exclusive within block
    if (t == 255) g_bsum[blockIdx.x] = sh[255];
}
__global__ void k_scan2() {
    __shared__ int sh[256];
    int t = threadIdx.x;
    int v = (t < SCAN_BLOCKS) ? g_bsum[t] : 0;
    sh[t] = v; __syncthreads();
    for (int off = 1; off < 256; off <<= 1) {
        int u = (t >= off) ? sh[t - off] : 0;
        __syncthreads();
        sh[t] += u;
        __syncthreads();
    }
    if (t < SCAN_BLOCKS) g_bsum[t] = sh[t] - v;  // exclusive block offsets
}
__global__ void k_scan3() {
    int i = blockIdx.x * blockDim.x + threadIdx.x;
    if (i >= Nn) return;
    int s = g_start[i] + g_bsum[i >> 8];
    g_start[i] = s;
    g_cursor[i] = s;
}

// ---------------- CSR scatter ----------------
__global__ void k_scatter(const int* __restrict__ node_out) {
    int e = blockIdx.x * blockDim.x + threadIdx.x;
    if (e >= Ee) return;
    int n = node_out[e];
    int p = atomicAdd(&g_cursor[n], 1);
    g_edges[p] = e;
}

// ---------------- scale = log(deg) / mean(log(deg)) ----------------
__global__ void k_scale1() {
    int i = blockIdx.x * blockDim.x + threadIdx.x;
    float s = 0.0f;
    if (i < Nn) {
        s = logf(g_deg[i]);
        g_scale[i] = s;
    }
    // warp reduce then atomic
    for (int o = 16; o; o >>= 1) s += __shfl_xor_sync(0xffffffffu, s, o);
    __shared__ float wsum[8];
    int lane = threadIdx.x & 31, wid = threadIdx.x >> 5;
    if (lane == 0) wsum[wid] = s;
    __syncthreads();
    if (threadIdx.x == 0) {
        float t = 0.0f;
        for (int w = 0; w < 8; w++) t += wsum[w];
        atomicAdd(&g_sum, t);
    }
}
__global__ void k_scale2() {
    int i = blockIdx.x * blockDim.x + threadIdx.x;
    if (i >= Nn) return;
    g_scale[i] = g_scale[i] * ((float)Nn / g_sum);
}

// ---------------- rel_input for all layers: query @ rel_W[i] + rel_b[i] ----------------
__global__ void k_rel(const float* __restrict__ q, const float* __restrict__ relW,
                      const float* __restrict__ relb) {
    int t = threadIdx.x;
    if (t >= NL * Dd) return;
    int i = t >> 5, d = t & 31;
    float acc = relb[i * Dd + d];
    for (int k = 0; k < Dd; k++)
        acc += q[k] * relW[(i * Dd + k) * Dd + d];
    g_rel[i * Dd + d] = acc;
}

// ---------------- expand lin_W into Wc (once) ----------------
// X row layout: [h(32) | feats(128)], feats index f = 4*dd + {mean,max,min,std}
// hidden[d] = Y[d] + s*Y[32+d] + inv*Y[64+d] + b[d]
__global__ void k_buildW(const float* __restrict__ linW) {
    int idx = blockIdx.x * blockDim.x + threadIdx.x;
    if (idx >= NL * KK * CN) return;
    int l = idx / (KK * CN);
    int rem = idx % (KK * CN);
    int k = rem / CN;
    int j = rem % CN;
    float v;
    if (k < 32) {
        v = (j < 32) ? linW[(l * 416 + k) * 32 + j] : 0.0f;
    } else {
        int f = k - 32, g = j >> 5, d = j & 31;
        v = linW[(l * 416 + 32 + f * 3 + g) * 32 + d];
    }
    g_Wc[idx] = v;
}

// ---------------- per-layer aggregation: warp per node, lane = dim ----------------
__global__ void k_agg(const int* __restrict__ node_in, const float* __restrict__ ew,
                      const int* __restrict__ hptr, int insel, int layer, int last) {
    int warp = (blockIdx.x * blockDim.x + threadIdx.x) >> 5;
    int lane = threadIdx.x & 31;
    if (warp >= Nn) return;
    int n = warp;
    const float* __restrict__ hin = hbuf(insel);
    int h = *hptr;
    float rel = g_rel[layer * Dd + lane];

    // self-loop message = boundary[n] (raw, weight 1)
    float b = (n == h) ? 0.0f : 100.0f;
    float sum = b, sq = b * b, mx = b, mn = b;
    float bestS = 32.0f * b;  // self-loop score = sum over dims
    int bestSrc = n;

    int st = g_start[n];
    int cnt = g_indeg[n];
    for (int j = 0; j < cnt; j++) {
        int e = g_edges[st + j];
        int src = node_in[e];
        float w = ew[e];
        float m = hin[src * Dd + lane] * rel;
        float wm = m * w;
        sum += wm;
        sq += m * m * w;
        mx = fmaxf(mx, wm);
        mn = fminf(mn, wm);
        if (last) {
            float sc = wm;
            #pragma unroll
            for (int o = 16; o; o >>= 1) sc += __shfl_xor_sync(0xffffffffu, sc, o);
            if (sc > bestS) { bestS = sc; bestSrc = src; }
            else if (sc == bestS) bestSrc = min(bestSrc, src);
        }
    }
    float c = (float)(cnt + 1);
    float mean = sum / c;
    float sqm = sq / c;
    float sd = sqrtf(fmaxf(sqm - mean * mean, 1e-6f));

    g_X[n * KK + lane] = hin[n * Dd + lane];
    float4 f4 = make_float4(mean, mx, mn, sd);
    *reinterpret_cast<float4*>(&g_X[n * KK + Dd + lane * 4]) = f4;

    if (last && lane == 0) g_pred[n] = bestSrc;
}

// ---------------- per-layer GEMM: Y = X(N x 160) @ Wc(160 x 96), fused epilogue ----------------
#define BM 64
#define ASTRIDE 65
__global__ void k_gemm(const float* __restrict__ linb, int layer, int outsel) {
    __shared__ float As[32 * ASTRIDE];   // [k][row], padded
    __shared__ float Bs[32 * CN];        // [k][col]
    __shared__ float Cs[BM * CN];
    float* __restrict__ hout = hbuf(outsel);

    int row0 = blockIdx.x * BM;
    int tx = threadIdx.x & 15;   // 16 across (6 cols each)
    int ty = threadIdx.x >> 4;   // 16 down (4 rows each)

    float acc[4][6];
    #pragma unroll
    for (int r = 0; r < 4; r++)
        #pragma unroll
        for (int c = 0; c < 6; c++) acc[r][c] = 0.0f;

    for (int kt = 0; kt < KK; kt += 32) {
        #pragma unroll
        for (int t = 0; t < 8; t++) {
            int idx = threadIdx.x + t * 256;   // 2048 A elements
            int r = idx >> 5, k = idx & 31;
            int row = row0 + r;
            As[k * ASTRIDE + r] = (row < Nn) ? g_X[row * KK + kt + k] : 0.0f;
        }
        #pragma unroll
        for (int t = 0; t < 12; t++) {
            int idx = threadIdx.x + t * 256;   // 3072 B elements
            int k = idx / CN, j = idx % CN;
            Bs[k * CN + j] = g_Wc[layer * KK * CN + (kt + k) * CN + j];
        }
        __syncthreads();
        #pragma unroll
        for (int k = 0; k < 32; k++) {
            float a[4], bb[6];
            #pragma unroll
            for (int r = 0; r < 4; r++) a[r] = As[k * ASTRIDE + ty * 4 + r];
            #pragma unroll
            for (int c = 0; c < 6; c++) bb[c] = Bs[k * CN + tx * 6 + c];
            #pragma unroll
            for (int r = 0; r < 4; r++)
                #pragma unroll
                for (int c = 0; c < 6; c++) acc[r][c] += a[r] * bb[c];
        }
        __syncthreads();
    }

    #pragma unroll
    for (int r = 0; r < 4; r++)
        #pragma unroll
        for (int c = 0; c < 6; c++)
            Cs[(ty * 4 + r) * CN + tx * 6 + c] = acc[r][c];
    __syncthreads();

    #pragma unroll
    for (int t = 0; t < 8; t++) {
        int idx = threadIdx.x + t * 256;   // 2048 outputs
        int r = idx >> 5, d = idx & 31;
        int n = row0 + r;
        if (n < Nn) {
            float s = g_scale[n];
            float inv = 1.0f / fmaxf(s, 0.01f);
            float v = Cs[r * CN + d] + s * Cs[r * CN + 32 + d] + inv * Cs[r * CN + 64 + d]
                      + linb[layer * Dd + d];
            hout[n * Dd + d] = fmaxf(v, 0.0f);
        }
    }
}

// ---------------- final MLP + output assembly ----------------
__global__ void k_final(int insel, const float* __restrict__ q,
                        const float* __restrict__ W1, const float* __restrict__ b1,
                        const float* __restrict__ W2, const float* __restrict__ b2,
                        float* __restrict__ out) {
    __shared__ float sW1[64 * 64];
    __shared__ float sW2[64];
    __shared__ float sb1[64];
    __shared__ float sq[32];
    int tid = threadIdx.x;
    for (int i = tid; i < 4096; i += 256) sW1[i] = W1[i];
    if (tid < 64) { sW2[tid] = W2[tid]; sb1[tid] = b1[tid]; }
    if (tid < 32) sq[tid] = q[tid];
    __syncthreads();

    const float* __restrict__ hfin = hbuf(insel);
    int warp = (blockIdx.x * blockDim.x + tid) >> 5;
    int lane = tid & 31;
    if (warp >= Nn) return;
    int n = warp;
    float hv = hfin[n * Dd + lane];
    float a0 = sb1[lane], a1 = sb1[lane + 32];
    #pragma unroll
    for (int k = 0; k < 32; k++) {
        float xv = __shfl_sync(0xffffffffu, hv, k);
        a0 += xv * sW1[k * 64 + lane];
        a1 += xv * sW1[k * 64 + 32 + lane];
    }
    #pragma unroll
    for (int k = 0; k < 32; k++) {
        float xv = sq[k];
        a0 += xv * sW1[(32 + k) * 64 + lane];
        a1 += xv * sW1[(32 + k) * 64 + 32 + lane];
    }
    a0 = fmaxf(a0, 0.0f);
    a1 = fmaxf(a1, 0.0f);
    float p = a0 * sW2[lane] + a1 * sW2[lane + 32];
    #pragma unroll
    for (int o = 16; o; o >>= 1) p += __shfl_xor_sync(0xffffffffu, p, o);
    if (lane == 0) {
        out[n] = p + b2[0];
        out[Nn + n] = (float)g_pred[n];
    }
}

// ---------------- launch ----------------
extern "C" void kernel_launch(void* const* d_in, const int* in_sizes, int n_in,
                              void* d_out, int out_size) {
    const int*   node_in  = (const int*)d_in[0];
    const int*   node_out = (const int*)d_in[1];
    const float* ew       = (const float*)d_in[2];
    const int*   hptr     = (const int*)d_in[3];
    const float* qw       = (const float*)d_in[4];
    const float* relW     = (const float*)d_in[5];
    const float* relb     = (const float*)d_in[6];
    const float* linW     = (const float*)d_in[7];
    const float* linb     = (const float*)d_in[8];
    const float* W1       = (const float*)d_in[9];
    const float* b1       = (const float*)d_in[10];
    const float* W2       = (const float*)d_in[11];
    const float* b2       = (const float*)d_in[12];
    float* out = (float*)d_out;

    k_init<<<(Nn * Dd + 255) / 256, 256>>>(hptr);
    k_count<<<(Ee + 255) / 256, 256>>>(node_out, ew);
    k_scan1<<<SCAN_BLOCKS, 256>>>();
    k_scan2<<<1, 256>>>();
    k_scan3<<<SCAN_BLOCKS, 256>>>();
    k_scatter<<<(Ee + 255) / 256, 256>>>(node_out);
    k_scale1<<<SCAN_BLOCKS, 256>>>();
    k_scale2<<<SCAN_BLOCKS, 256>>>();
    k_rel<<<1, 192>>>(qw, relW, relb);
    k_buildW<<<(NL * KK * CN + 255) / 256, 256>>>(linW);

    int cur = 0;
    for (int l = 0; l < NL; l++) {
        int last = (l == NL - 1) ? 1 : 0;
        k_agg<<<(Nn + 7) / 8, 256>>>(node_in, ew, hptr, cur, l, last);
        k_gemm<<<(Nn + BM - 1) / BM, 256>>>(linb, l, cur ^ 1);
        cur ^= 1;
    }
    k_final<<<(Nn + 7) / 8, 256>>>(cur, qw, W1, b1, W2, b2, out);
}

// round 2
// speedup vs baseline: 1.2511x; 1.2511x over previous
#include <cuda_runtime.h>
#include <cuda_bf16.h>
#include <mma.h>
#include <math.h>

using namespace nvcuda;

// Problem constants (fixed by the dataset)
#define Nn 50000
#define NR 50048          // Nn rounded up to BM multiple (391*128)
#define Ee 800000
#define Dd 32
#define NL 6
#define KK 160            // GEMM K: 32 (h) + 128 (feats)
#define CN 96             // GEMM N: 3 groups of 32 (base, *scale, *inv_scale)
#define SCAN_BLOCKS 196   // ceil(Nn/256)
#define BM 128            // GEMM block rows
#define A_LD 40           // padded A smem leading dim (bf16 elems)
#define B_LD 104          // padded B smem leading dim (bf16 elems)
#define GEMM_SMEM ((2*KK*B_LD + 2*BM*A_LD) * 2)   // 87040 bytes

// ---------------- device scratch (no allocations allowed) ----------------
__device__ float g_h0[Nn * Dd];
__device__ float g_h1[Nn * Dd];
__device__ __nv_bfloat16 g_Xh[NR * KK];     // GEMM input rows, bf16 hi
__device__ __nv_bfloat16 g_Xl[NR * KK];     // GEMM input rows, bf16 lo
__device__ __nv_bfloat16 g_Wbh[NL * KK * CN];
__device__ __nv_bfloat16 g_Wbl[NL * KK * CN];
__device__ float g_scale[Nn];
__device__ float g_deg[Nn];
__device__ int   g_indeg[Nn];
__device__ int   g_start[Nn];
__device__ int   g_cursor[Nn];
__device__ int   g_csr_src[Ee];
__device__ float g_csr_w[Ee];
__device__ float g_rel[NL * Dd];
__device__ float g_sum;
__device__ int   g_pred[Nn];
__device__ int   g_bsum[256];

__device__ __forceinline__ float* hbuf(int s) { return s ? g_h1 : g_h0; }

// ---------------- init: boundary layer input, degree, counters ----------------
__global__ void k_init(const int* __restrict__ hptr) {
    int idx = blockIdx.x * blockDim.x + threadIdx.x;
    if (idx >= Nn * Dd) return;
    int n = idx >> 5;
    int h = *hptr;
    g_h0[idx] = (n == h) ? 0.0f : 100.0f;
    if ((idx & 31) == 0) {
        g_deg[n] = 1.0f;
        g_indeg[n] = 0;
    }
    if (idx == 0) g_sum = 0.0f;
}

// ---------------- edge counting ----------------
__global__ void k_count(const int* __restrict__ node_out, const float* __restrict__ ew) {
    int e = blockIdx.x * blockDim.x + threadIdx.x;
    if (e >= Ee) return;
    int o = node_out[e];
    atomicAdd(&g_deg[o], ew[e]);
    atomicAdd(&g_indeg[o], 1);
}

// ---------------- 3-phase exclusive scan over g_indeg ----------------
__global__ void k_scan1() {
    __shared__ int sh[256];
    int i = blockIdx.x * 256 + threadIdx.x;
    int t = threadIdx.x;
    int v = (i < Nn) ? g_indeg[i] : 0;
    sh[t] = v; __syncthreads();
    for (int off = 1; off < 256; off <<= 1) {
        int u = (t >= off) ? sh[t - off] : 0;
        __syncthreads();
        sh[t] += u;
        __syncthreads();
    }
    if (i < Nn) g_start[i] = sh[t] - v;
    if (t == 255) g_bsum[blockIdx.x] = sh[255];
}
__global__ void k_scan2() {
    __shared__ int sh[256];
    int t = threadIdx.x;
    int v = (t < SCAN_BLOCKS) ? g_bsum[t] : 0;
    sh[t] = v; __syncthreads();
    for (int off = 1; off < 256; off <<= 1) {
        int u = (t >= off) ? sh[t - off] : 0;
        __syncthreads();
        sh[t] += u;
        __syncthreads();
    }
    if (t < SCAN_BLOCKS) g_bsum[t] = sh[t] - v;
}
__global__ void k_scan3() {
    int i = blockIdx.x * blockDim.x + threadIdx.x;
    if (i >= Nn) return;
    int s = g_start[i] + g_bsum[i >> 8];
    g_start[i] = s;
    g_cursor[i] = s;
}

// ---------------- CSR scatter: store (src, weight) directly ----------------
__global__ void k_scatter(const int* __restrict__ node_out, const int* __restrict__ node_in,
                          const float* __restrict__ ew) {
    int e = blockIdx.x * blockDim.x + threadIdx.x;
    if (e >= Ee) return;
    int n = node_out[e];
    int p = atomicAdd(&g_cursor[n], 1);
    g_csr_src[p] = node_in[e];
    g_csr_w[p] = ew[e];
}

// ---------------- scale = log(deg) / mean(log(deg)) ----------------
__global__ void k_scale1() {
    int i = blockIdx.x * blockDim.x + threadIdx.x;
    float s = 0.0f;
    if (i < Nn) {
        s = logf(g_deg[i]);
        g_scale[i] = s;
    }
    for (int o = 16; o; o >>= 1) s += __shfl_xor_sync(0xffffffffu, s, o);
    __shared__ float wsum[8];
    int lane = threadIdx.x & 31, wid = threadIdx.x >> 5;
    if (lane == 0) wsum[wid] = s;
    __syncthreads();
    if (threadIdx.x == 0) {
        float t = 0.0f;
        for (int w = 0; w < 8; w++) t += wsum[w];
        atomicAdd(&g_sum, t);
    }
}
__global__ void k_scale2() {
    int i = blockIdx.x * blockDim.x + threadIdx.x;
    if (i >= Nn) return;
    g_scale[i] = g_scale[i] * ((float)Nn / g_sum);
}

// ---------------- rel_input for all layers ----------------
__global__ void k_rel(const float* __restrict__ q, const float* __restrict__ relW,
                      const float* __restrict__ relb) {
    int t = threadIdx.x;
    if (t >= NL * Dd) return;
    int i = t >> 5, d = t & 31;
    float acc = relb[i * Dd + d];
    for (int k = 0; k < Dd; k++)
        acc += q[k] * relW[(i * Dd + k) * Dd + d];
    g_rel[i * Dd + d] = acc;
}

// ---------------- expand lin_W into split-bf16 Wc (once) ----------------
__global__ void k_buildW(const float* __restrict__ linW) {
    int idx = blockIdx.x * blockDim.x + threadIdx.x;
    if (idx >= NL * KK * CN) return;
    int l = idx / (KK * CN);
    int rem = idx % (KK * CN);
    int k = rem / CN;
    int j = rem % CN;
    float v;
    if (k < 32) {
        v = (j < 32) ? linW[(l * 416 + k) * 32 + j] : 0.0f;
    } else {
        int f = k - 32, g = j >> 5, d = j & 31;
        v = linW[(l * 416 + 32 + f * 3 + g) * 32 + d];
    }
    __nv_bfloat16 h = __float2bfloat16_rn(v);
    g_Wbh[idx] = h;
    g_Wbl[idx] = __float2bfloat16_rn(v - __bfloat162float(h));
}

// ---------------- per-layer aggregation: warp per node, lane = dim ----------------
__global__ void k_agg(const int* __restrict__ hptr, int insel, int layer, int last) {
    int warp = (blockIdx.x * blockDim.x + threadIdx.x) >> 5;
    int lane = threadIdx.x & 31;
    if (warp >= Nn) return;
    int n = warp;
    const float* __restrict__ hin = hbuf(insel);
    int h = *hptr;
    float rel = g_rel[layer * Dd + lane];

    float b = (n == h) ? 0.0f : 100.0f;
    float sum = b, sq = b * b, mx = b, mn = b;
    float bestS = 32.0f * b;
    int bestSrc = n;

    int st = g_start[n];
    int cnt = g_indeg[n];
    for (int base = 0; base < cnt; base += 32) {
        int rem = cnt - base;
        int m = rem < 32 ? rem : 32;
        int srcL = 0; float wL = 0.0f;
        if (lane < m) {
            srcL = g_csr_src[st + base + lane];
            wL   = g_csr_w[st + base + lane];
        }
        for (int j = 0; j < m; j++) {
            int src = __shfl_sync(0xffffffffu, srcL, j);
            float w = __shfl_sync(0xffffffffu, wL, j);
            float mv = hin[src * Dd + lane] * rel;
            float wm = mv * w;
            sum += wm;
            sq += mv * mv * w;
            mx = fmaxf(mx, wm);
            mn = fminf(mn, wm);
            if (last) {
                float sc = wm;
                #pragma unroll
                for (int o = 16; o; o >>= 1) sc += __shfl_xor_sync(0xffffffffu, sc, o);
                if (sc > bestS) { bestS = sc; bestSrc = src; }
                else if (sc == bestS) bestSrc = min(bestSrc, src);
            }
        }
    }
    float c = (float)(cnt + 1);
    float mean = sum / c;
    float sqm = sq / c;
    float sd = sqrtf(fmaxf(sqm - mean * mean, 1e-6f));

    // write split-bf16 GEMM row: [h(32) | feats(128)]
    float hv = hin[n * Dd + lane];
    __nv_bfloat16 hh = __float2bfloat16_rn(hv);
    g_Xh[n * KK + lane] = hh;
    g_Xl[n * KK + lane] = __float2bfloat16_rn(hv - __bfloat162float(hh));

    union { __nv_bfloat16 v[4]; uint2 u; } ph, pl;
    float fv[4] = {mean, mx, mn, sd};
    #pragma unroll
    for (int t = 0; t < 4; t++) {
        __nv_bfloat16 fh = __float2bfloat16_rn(fv[t]);
        ph.v[t] = fh;
        pl.v[t] = __float2bfloat16_rn(fv[t] - __bfloat162float(fh));
    }
    *reinterpret_cast<uint2*>(&g_Xh[n * KK + Dd + lane * 4]) = ph.u;
    *reinterpret_cast<uint2*>(&g_Xl[n * KK + Dd + lane * 4]) = pl.u;

    if (last && lane == 0) g_pred[n] = bestSrc;
}

// ---------------- tensor-core GEMM: Y = X(N x 160) @ Wc(160 x 96) + fused epilogue ----
// bf16 split (3-term): X = Xh + Xl, W = Wh + Wl; Y ~= Xh*Wh + Xh*Wl + Xl*Wh
__global__ void k_gemm(const float* __restrict__ linb, int layer, int outsel) {
    extern __shared__ char sm_[];
    __nv_bfloat16* Bh = reinterpret_cast<__nv_bfloat16*>(sm_);          // KK x B_LD
    __nv_bfloat16* Bl = Bh + KK * B_LD;
    __nv_bfloat16* Ah = Bl + KK * B_LD;                                 // BM x A_LD
    __nv_bfloat16* Al = Ah + BM * A_LD;
    float* Cs = reinterpret_cast<float*>(sm_);                          // reuse: BM x CN

    float* __restrict__ hout = hbuf(outsel);
    int row0 = blockIdx.x * BM;
    int wid = threadIdx.x >> 5;

    // load full B (hi/lo) into smem: 160x96, vectorized 8 bf16
    {
        const uint4* srcH = reinterpret_cast<const uint4*>(g_Wbh + layer * KK * CN);
        const uint4* srcL = reinterpret_cast<const uint4*>(g_Wbl + layer * KK * CN);
        for (int i = threadIdx.x; i < KK * CN / 8; i += 256) {
            int r = i / 12, c = i % 12;
            reinterpret_cast<uint4*>(Bh + r * B_LD)[c] = srcH[i];
            reinterpret_cast<uint4*>(Bl + r * B_LD)[c] = srcL[i];
        }
    }

    wmma::fragment<wmma::accumulator, 16, 16, 16, float> acc[6];
    #pragma unroll
    for (int t = 0; t < 6; t++) wmma::fill_fragment(acc[t], 0.0f);

    for (int kt = 0; kt < KK; kt += 32) {
        __syncthreads();
        // load A chunk (BM x 32) hi/lo
        for (int i = threadIdx.x; i < BM * 32 / 8; i += 256) {   // 512 uint4 per array
            int r = i >> 2, c = i & 3;
            size_t goff = (size_t)(row0 + r) * KK + kt + c * 8;
            reinterpret_cast<uint4*>(Ah + r * A_LD)[c] =
                *reinterpret_cast<const uint4*>(g_Xh + goff);
            reinterpret_cast<uint4*>(Al + r * A_LD)[c] =
                *reinterpret_cast<const uint4*>(g_Xl + goff);
        }
        __syncthreads();

        #pragma unroll
        for (int ks = 0; ks < 32; ks += 16) {
            wmma::fragment<wmma::matrix_a, 16, 16, 16, __nv_bfloat16, wmma::row_major> ah, al;
            wmma::load_matrix_sync(ah, Ah + wid * 16 * A_LD + ks, A_LD);
            wmma::load_matrix_sync(al, Al + wid * 16 * A_LD + ks, A_LD);
            #pragma unroll
            for (int t = 0; t < 6; t++) {
                wmma::fragment<wmma::matrix_b, 16, 16, 16, __nv_bfloat16, wmma::row_major> bh, bl;
                wmma::load_matrix_sync(bh, Bh + (kt + ks) * B_LD + t * 16, B_LD);
                wmma::load_matrix_sync(bl, Bl + (kt + ks) * B_LD + t * 16, B_LD);
                wmma::mma_sync(acc[t], ah, bh, acc[t]);
                wmma::mma_sync(acc[t], ah, bl, acc[t]);
                wmma::mma_sync(acc[t], al, bh, acc[t]);
            }
        }
    }

    __syncthreads();
    #pragma unroll
    for (int t = 0; t < 6; t++)
        wmma::store_matrix_sync(Cs + wid * 16 * CN + t * 16, acc[t], CN, wmma::mem_row_major);
    __syncthreads();

    for (int i = threadIdx.x; i < BM * Dd; i += 256) {
        int r = i >> 5, d = i & 31;
        int n = row0 + r;
        if (n < Nn) {
            float s = g_scale[n];
            float inv = 1.0f / fmaxf(s, 0.01f);
            float v = Cs[r * CN + d] + s * Cs[r * CN + 32 + d] + inv * Cs[r * CN + 64 + d]
                      + linb[layer * Dd + d];
            hout[n * Dd + d] = fmaxf(v, 0.0f);
        }
    }
}

// ---------------- final MLP + output assembly ----------------
__global__ void k_final(int insel, const float* __restrict__ q,
                        const float* __restrict__ W1, const float* __restrict__ b1,
                        const float* __restrict__ W2, const float* __restrict__ b2,
                        float* __restrict__ out) {
    __shared__ float sW1[64 * 64];
    __shared__ float sW2[64];
    __shared__ float sb1[64];
    __shared__ float sq[32];
    int tid = threadIdx.x;
    for (int i = tid; i < 4096; i += 256) sW1[i] = W1[i];
    if (tid < 64) { sW2[tid] = W2[tid]; sb1[tid] = b1[tid]; }
    if (tid < 32) sq[tid] = q[tid];
    __syncthreads();

    const float* __restrict__ hfin = hbuf(insel);
    int warp = (blockIdx.x * blockDim.x + tid) >> 5;
    int lane = tid & 31;
    if (warp >= Nn) return;
    int n = warp;
    float hv = hfin[n * Dd + lane];
    float a0 = sb1[lane], a1 = sb1[lane + 32];
    #pragma unroll
    for (int k = 0; k < 32; k++) {
        float xv = __shfl_sync(0xffffffffu, hv, k);
        a0 += xv * sW1[k * 64 + lane];
        a1 += xv * sW1[k * 64 + 32 + lane];
    }
    #pragma unroll
    for (int k = 0; k < 32; k++) {
        float xv = sq[k];
        a0 += xv * sW1[(32 + k) * 64 + lane];
        a1 += xv * sW1[(32 + k) * 64 + 32 + lane];
    }
    a0 = fmaxf(a0, 0.0f);
    a1 = fmaxf(a1, 0.0f);
    float p = a0 * sW2[lane] + a1 * sW2[lane + 32];
    #pragma unroll
    for (int o = 16; o; o >>= 1) p += __shfl_xor_sync(0xffffffffu, p, o);
    if (lane == 0) {
        out[n] = p + b2[0];
        out[Nn + n] = (float)g_pred[n];
    }
}

// ---------------- launch ----------------
extern "C" void kernel_launch(void* const* d_in, const int* in_sizes, int n_in,
                              void* d_out, int out_size) {
    const int*   node_in  = (const int*)d_in[0];
    const int*   node_out = (const int*)d_in[1];
    const float* ew       = (const float*)d_in[2];
    const int*   hptr     = (const int*)d_in[3];
    const float* qw       = (const float*)d_in[4];
    const float* relW     = (const float*)d_in[5];
    const float* relb     = (const float*)d_in[6];
    const float* linW     = (const float*)d_in[7];
    const float* linb     = (const float*)d_in[8];
    const float* W1       = (const float*)d_in[9];
    const float* b1       = (const float*)d_in[10];
    const float* W2       = (const float*)d_in[11];
    const float* b2       = (const float*)d_in[12];
    float* out = (float*)d_out;

    static bool attr_set = false;
    if (!attr_set) {
        cudaFuncSetAttribute(k_gemm, cudaFuncAttributeMaxDynamicSharedMemorySize, GEMM_SMEM);
        attr_set = true;
    }

    k_init<<<(Nn * Dd + 255) / 256, 256>>>(hptr);
    k_count<<<(Ee + 255) / 256, 256>>>(node_out, ew);
    k_scan1<<<SCAN_BLOCKS, 256>>>();
    k_scan2<<<1, 256>>>();
    k_scan3<<<SCAN_BLOCKS, 256>>>();
    k_scatter<<<(Ee + 255) / 256, 256>>>(node_out, node_in, ew);
    k_scale1<<<SCAN_BLOCKS, 256>>>();
    k_scale2<<<SCAN_BLOCKS, 256>>>();
    k_rel<<<1, 192>>>(qw, relW, relb);
    k_buildW<<<(NL * KK * CN + 255) / 256, 256>>>(linW);

    int cur = 0;
    for (int l = 0; l < NL; l++) {
        int last = (l == NL - 1) ? 1 : 0;
        k_agg<<<(Nn + 7) / 8, 256>>>(hptr, cur, l, last);
        k_gemm<<<(NR / BM), 256, GEMM_SMEM>>>(linb, l, cur ^ 1);
        cur ^= 1;
    }
    k_final<<<(Nn + 7) / 8, 256>>>(cur, qw, W1, b1, W2, b2, out);
}

// round 3
// speedup vs baseline: 1.3485x; 1.0778x over previous
#include <cuda_runtime.h>
#include <cuda_bf16.h>
#include <mma.h>
#include <math.h>

using namespace nvcuda;

// Problem constants (fixed by the dataset)
#define Nn 50000
#define NR 50048          // Nn rounded up to BM multiple (391*128)
#define Ee 800000
#define Dd 32
#define NL 6
#define KK 160            // GEMM K: 32 (h) + 128 (feats)
#define CN 96             // GEMM N: 3 groups of 32 (base, *scale, *inv_scale)
#define BM 128            // GEMM block rows
#define A_LD 40           // padded A smem leading dim (bf16 elems)
#define B_LD 104          // padded B smem leading dim (bf16 elems)
#define GEMM_SMEM ((2*KK*B_LD + 2*BM*A_LD) * 2)   // 87040 bytes

// ---------------- device scratch (no allocations allowed) ----------------
__device__ float g_h0[Nn * Dd];
__device__ float g_h1[Nn * Dd];
__device__ __nv_bfloat16 g_Xh[NR * KK];
__device__ __nv_bfloat16 g_Xl[NR * KK];
__device__ __nv_bfloat16 g_Wbh[NL * KK * CN];
__device__ __nv_bfloat16 g_Wbl[NL * KK * CN];
__device__ float g_scale[Nn];
__device__ float g_deg[Nn];
__device__ int   g_indeg[Nn];
__device__ int   g_start[Nn];
__device__ int   g_cursor[Nn];
__device__ int2  g_csr[Ee];        // (src, weight bits)
__device__ float g_rel[NL * Dd];
__device__ float g_D[Nn];          // per-node dot(h, rel) for last layer score
__device__ float g_sum;
__device__ int   g_tot;
__device__ int   g_pred[Nn];

__device__ __forceinline__ float* hbuf(int s) { return s ? g_h1 : g_h0; }

// ---------------- init: boundary, deg/indeg reset, rel precompute ----------------
__global__ void k_init(const int* __restrict__ hptr, const float* __restrict__ q,
                       const float* __restrict__ relW, const float* __restrict__ relb) {
    int idx = blockIdx.x * blockDim.x + threadIdx.x;
    if (idx < Nn * Dd) {
        int n = idx >> 5;
        int h = *hptr;
        g_h0[idx] = (n == h) ? 0.0f : 100.0f;
        if ((idx & 31) == 0) {
            g_deg[n] = 1.0f;
            g_indeg[n] = 0;
        }
    }
    if (idx < NL * Dd) {
        int i = idx >> 5, d = idx & 31;
        float acc = relb[i * Dd + d];
        for (int k = 0; k < Dd; k++)
            acc += q[k] * relW[(i * Dd + k) * Dd + d];
        g_rel[i * Dd + d] = acc;
    }
    if (idx == 0) { g_sum = 0.0f; g_tot = 0; }
}

// ---------------- edge counting ----------------
__global__ void k_count(const int* __restrict__ node_out, const float* __restrict__ ew) {
    int e = blockIdx.x * blockDim.x + threadIdx.x;
    if (e >= Ee) return;
    int o = node_out[e];
    atomicAdd(&g_deg[o], ew[e]);
    atomicAdd(&g_indeg[o], 1);
}

// ---------------- segment allocation via atomics (replaces 3-kernel scan) ------
__global__ void k_alloc() {
    int i = blockIdx.x * blockDim.x + threadIdx.x;
    if (i >= Nn) return;
    int c = g_indeg[i];
    int st = atomicAdd(&g_tot, c);
    g_start[i] = st;
    g_cursor[i] = st;
}

// ---------------- CSR scatter: (src, weight) packed ----------------
__global__ void k_scatter(const int* __restrict__ node_out, const int* __restrict__ node_in,
                          const float* __restrict__ ew) {
    int e = blockIdx.x * blockDim.x + threadIdx.x;
    if (e >= Ee) return;
    int n = node_out[e];
    int p = atomicAdd(&g_cursor[n], 1);
    g_csr[p] = make_int2(node_in[e], __float_as_int(ew[e]));
}

// ---------------- scale = log(deg) / mean(log(deg)) ----------------
__global__ void k_scale1() {
    int i = blockIdx.x * blockDim.x + threadIdx.x;
    float s = 0.0f;
    if (i < Nn) {
        s = logf(g_deg[i]);
        g_scale[i] = s;
    }
    for (int o = 16; o; o >>= 1) s += __shfl_xor_sync(0xffffffffu, s, o);
    __shared__ float wsum[8];
    int lane = threadIdx.x & 31, wid = threadIdx.x >> 5;
    if (lane == 0) wsum[wid] = s;
    __syncthreads();
    if (threadIdx.x == 0) {
        float t = 0.0f;
        for (int w = 0; w < 8; w++) t += wsum[w];
        atomicAdd(&g_sum, t);
    }
}
__global__ void k_scale2() {
    int i = blockIdx.x * blockDim.x + threadIdx.x;
    if (i >= Nn) return;
    g_scale[i] = g_scale[i] * ((float)Nn / g_sum);
}

// ---------------- expand lin_W into split-bf16 Wc (once) ----------------
__global__ void k_buildW(const float* __restrict__ linW) {
    int idx = blockIdx.x * blockDim.x + threadIdx.x;
    if (idx >= NL * KK * CN) return;
    int l = idx / (KK * CN);
    int rem = idx % (KK * CN);
    int k = rem / CN;
    int j = rem % CN;
    float v;
    if (k < 32) {
        v = (j < 32) ? linW[(l * 416 + k) * 32 + j] : 0.0f;
    } else {
        int f = k - 32, g = j >> 5, d = j & 31;
        v = linW[(l * 416 + 32 + f * 3 + g) * 32 + d];
    }
    __nv_bfloat16 h = __float2bfloat16_rn(v);
    g_Wbh[idx] = h;
    g_Wbl[idx] = __float2bfloat16_rn(v - __bfloat162float(h));
}

// ---------------- per-node dot(h, rel) for last-layer scores ----------------
__global__ void k_dot(int insel, int layer) {
    int warp = (blockIdx.x * blockDim.x + threadIdx.x) >> 5;
    int lane = threadIdx.x & 31;
    if (warp >= Nn) return;
    const float* __restrict__ hin = hbuf(insel);
    float v = hin[warp * Dd + lane] * g_rel[layer * Dd + lane];
    #pragma unroll
    for (int o = 16; o; o >>= 1) v += __shfl_xor_sync(0xffffffffu, v, o);
    if (lane == 0) g_D[warp] = v;
}

// ---------------- per-layer aggregation: warp per node, lane = dim ----------------
template <int LAST>
__global__ void k_agg(const int* __restrict__ hptr, int insel, int layer) {
    int warp = (blockIdx.x * blockDim.x + threadIdx.x) >> 5;
    int lane = threadIdx.x & 31;
    if (warp >= Nn) return;
    int n = warp;
    const float* __restrict__ hin = hbuf(insel);
    int h = *hptr;
    float relv = g_rel[layer * Dd + lane];

    float b = (n == h) ? 0.0f : 100.0f;
    float sum = b, sq = b * b, mx = b, mn = b;
    float bestS = 32.0f * b;
    int bestSrc = n;

    int st = g_start[n];
    int cnt = g_indeg[n];
    for (int base = 0; base < cnt; base += 32) {
        int rem = cnt - base;
        int m = rem < 32 ? rem : 32;
        int2 ed = make_int2(0, 0);
        if (lane < m) ed = g_csr[st + base + lane];

        int j = 0;
        for (; j + 4 <= m; j += 4) {
            int s0 = __shfl_sync(0xffffffffu, ed.x, j + 0);
            int s1 = __shfl_sync(0xffffffffu, ed.x, j + 1);
            int s2 = __shfl_sync(0xffffffffu, ed.x, j + 2);
            int s3 = __shfl_sync(0xffffffffu, ed.x, j + 3);
            float w0 = __int_as_float(__shfl_sync(0xffffffffu, ed.y, j + 0));
            float w1 = __int_as_float(__shfl_sync(0xffffffffu, ed.y, j + 1));
            float w2 = __int_as_float(__shfl_sync(0xffffffffu, ed.y, j + 2));
            float w3 = __int_as_float(__shfl_sync(0xffffffffu, ed.y, j + 3));
            // issue all gathers before accumulating (MLP=4)
            float v0 = hin[s0 * Dd + lane];
            float v1 = hin[s1 * Dd + lane];
            float v2 = hin[s2 * Dd + lane];
            float v3 = hin[s3 * Dd + lane];
            float D0 = 0.f, D1 = 0.f, D2 = 0.f, D3 = 0.f;
            if (LAST) { D0 = g_D[s0]; D1 = g_D[s1]; D2 = g_D[s2]; D3 = g_D[s3]; }

            float m0 = v0 * relv, wm0 = m0 * w0;
            sum += wm0; sq += m0 * m0 * w0;
            mx = fmaxf(mx, wm0); mn = fminf(mn, wm0);
            float m1 = v1 * relv, wm1 = m1 * w1;
            sum += wm1; sq += m1 * m1 * w1;
            mx = fmaxf(mx, wm1); mn = fminf(mn, wm1);
            float m2 = v2 * relv, wm2 = m2 * w2;
            sum += wm2; sq += m2 * m2 * w2;
            mx = fmaxf(mx, wm2); mn = fminf(mn, wm2);
            float m3 = v3 * relv, wm3 = m3 * w3;
            sum += wm3; sq += m3 * m3 * w3;
            mx = fmaxf(mx, wm3); mn = fminf(mn, wm3);

            if (LAST) {
                float sc0 = w0 * D0, sc1 = w1 * D1, sc2 = w2 * D2, sc3 = w3 * D3;
                if (sc0 > bestS) { bestS = sc0; bestSrc = s0; }
                else if (sc0 == bestS) bestSrc = min(bestSrc, s0);
                if (sc1 > bestS) { bestS = sc1; bestSrc = s1; }
                else if (sc1 == bestS) bestSrc = min(bestSrc, s1);
                if (sc2 > bestS) { bestS = sc2; bestSrc = s2; }
                else if (sc2 == bestS) bestSrc = min(bestSrc, s2);
                if (sc3 > bestS) { bestS = sc3; bestSrc = s3; }
                else if (sc3 == bestS) bestSrc = min(bestSrc, s3);
            }
        }
        for (; j < m; j++) {
            int s0 = __shfl_sync(0xffffffffu, ed.x, j);
            float w0 = __int_as_float(__shfl_sync(0xffffffffu, ed.y, j));
            float m0 = hin[s0 * Dd + lane] * relv;
            float wm0 = m0 * w0;
            sum += wm0; sq += m0 * m0 * w0;
            mx = fmaxf(mx, wm0); mn = fminf(mn, wm0);
            if (LAST) {
                float sc = w0 * g_D[s0];
                if (sc > bestS) { bestS = sc; bestSrc = s0; }
                else if (sc == bestS) bestSrc = min(bestSrc, s0);
            }
        }
    }
    float c = (float)(cnt + 1);
    float mean = sum / c;
    float sqm = sq / c;
    float sd = sqrtf(fmaxf(sqm - mean * mean, 1e-6f));

    // write split-bf16 GEMM row: [h(32) | feats(128)]
    float hv = hin[n * Dd + lane];
    __nv_bfloat16 hh = __float2bfloat16_rn(hv);
    g_Xh[n * KK + lane] = hh;
    g_Xl[n * KK + lane] = __float2bfloat16_rn(hv - __bfloat162float(hh));

    union { __nv_bfloat16 v[4]; uint2 u; } ph, pl;
    float fv[4] = {mean, mx, mn, sd};
    #pragma unroll
    for (int t = 0; t < 4; t++) {
        __nv_bfloat16 fh = __float2bfloat16_rn(fv[t]);
        ph.v[t] = fh;
        pl.v[t] = __float2bfloat16_rn(fv[t] - __bfloat162float(fh));
    }
    *reinterpret_cast<uint2*>(&g_Xh[n * KK + Dd + lane * 4]) = ph.u;
    *reinterpret_cast<uint2*>(&g_Xl[n * KK + Dd + lane * 4]) = pl.u;

    if (LAST && lane == 0) g_pred[n] = bestSrc;
}

// ---------------- tensor-core GEMM: Y = X(N x 160) @ Wc(160 x 96) + fused epilogue ----
__global__ void k_gemm(const float* __restrict__ linb, int layer, int outsel) {
    extern __shared__ char sm_[];
    __nv_bfloat16* Bh = reinterpret_cast<__nv_bfloat16*>(sm_);
    __nv_bfloat16* Bl = Bh + KK * B_LD;
    __nv_bfloat16* Ah = Bl + KK * B_LD;
    __nv_bfloat16* Al = Ah + BM * A_LD;
    float* Cs = reinterpret_cast<float*>(sm_);

    float* __restrict__ hout = hbuf(outsel);
    int row0 = blockIdx.x * BM;
    int wid = threadIdx.x >> 5;

    {
        const uint4* srcH = reinterpret_cast<const uint4*>(g_Wbh + layer * KK * CN);
        const uint4* srcL = reinterpret_cast<const uint4*>(g_Wbl + layer * KK * CN);
        for (int i = threadIdx.x; i < KK * CN / 8; i += 256) {
            int r = i / 12, c = i % 12;
            reinterpret_cast<uint4*>(Bh + r * B_LD)[c] = srcH[i];
            reinterpret_cast<uint4*>(Bl + r * B_LD)[c] = srcL[i];
        }
    }

    wmma::fragment<wmma::accumulator, 16, 16, 16, float> acc[6];
    #pragma unroll
    for (int t = 0; t < 6; t++) wmma::fill_fragment(acc[t], 0.0f);

    for (int kt = 0; kt < KK; kt += 32) {
        __syncthreads();
        for (int i = threadIdx.x; i < BM * 32 / 8; i += 256) {
            int r = i >> 2, c = i & 3;
            size_t goff = (size_t)(row0 + r) * KK + kt + c * 8;
            reinterpret_cast<uint4*>(Ah + r * A_LD)[c] =
                *reinterpret_cast<const uint4*>(g_Xh + goff);
            reinterpret_cast<uint4*>(Al + r * A_LD)[c] =
                *reinterpret_cast<const uint4*>(g_Xl + goff);
        }
        __syncthreads();

        #pragma unroll
        for (int ks = 0; ks < 32; ks += 16) {
            wmma::fragment<wmma::matrix_a, 16, 16, 16, __nv_bfloat16, wmma::row_major> ah, al;
            wmma::load_matrix_sync(ah, Ah + wid * 16 * A_LD + ks, A_LD);
            wmma::load_matrix_sync(al, Al + wid * 16 * A_LD + ks, A_LD);
            #pragma unroll
            for (int t = 0; t < 6; t++) {
                wmma::fragment<wmma::matrix_b, 16, 16, 16, __nv_bfloat16, wmma::row_major> bh, bl;
                wmma::load_matrix_sync(bh, Bh + (kt + ks) * B_LD + t * 16, B_LD);
                wmma::load_matrix_sync(bl, Bl + (kt + ks) * B_LD + t * 16, B_LD);
                wmma::mma_sync(acc[t], ah, bh, acc[t]);
                wmma::mma_sync(acc[t], ah, bl, acc[t]);
                wmma::mma_sync(acc[t], al, bh, acc[t]);
            }
        }
    }

    __syncthreads();
    #pragma unroll
    for (int t = 0; t < 6; t++)
        wmma::store_matrix_sync(Cs + wid * 16 * CN + t * 16, acc[t], CN, wmma::mem_row_major);
    __syncthreads();

    for (int i = threadIdx.x; i < BM * Dd; i += 256) {
        int r = i >> 5, d = i & 31;
        int n = row0 + r;
        if (n < Nn) {
            float s = g_scale[n];
            float inv = 1.0f / fmaxf(s, 0.01f);
            float v = Cs[r * CN + d] + s * Cs[r * CN + 32 + d] + inv * Cs[r * CN + 64 + d]
                      + linb[layer * Dd + d];
            hout[n * Dd + d] = fmaxf(v, 0.0f);
        }
    }
}

// ---------------- final MLP + output assembly ----------------
__global__ void k_final(int insel, const float* __restrict__ q,
                        const float* __restrict__ W1, const float* __restrict__ b1,
                        const float* __restrict__ W2, const float* __restrict__ b2,
                        float* __restrict__ out) {
    __shared__ float sW1[64 * 64];
    __shared__ float sW2[64];
    __shared__ float sb1[64];
    __shared__ float sq[32];
    int tid = threadIdx.x;
    for (int i = tid; i < 4096; i += 256) sW1[i] = W1[i];
    if (tid < 64) { sW2[tid] = W2[tid]; sb1[tid] = b1[tid]; }
    if (tid < 32) sq[tid] = q[tid];
    __syncthreads();

    const float* __restrict__ hfin = hbuf(insel);
    int warp = (blockIdx.x * blockDim.x + tid) >> 5;
    int lane = tid & 31;
    if (warp >= Nn) return;
    int n = warp;
    float hv = hfin[n * Dd + lane];
    float a0 = sb1[lane], a1 = sb1[lane + 32];
    #pragma unroll
    for (int k = 0; k < 32; k++) {
        float xv = __shfl_sync(0xffffffffu, hv, k);
        a0 += xv * sW1[k * 64 + lane];
        a1 += xv * sW1[k * 64 + 32 + lane];
    }
    #pragma unroll
    for (int k = 0; k < 32; k++) {
        float xv = sq[k];
        a0 += xv * sW1[(32 + k) * 64 + lane];
        a1 += xv * sW1[(32 + k) * 64 + 32 + lane];
    }
    a0 = fmaxf(a0, 0.0f);
    a1 = fmaxf(a1, 0.0f);
    float p = a0 * sW2[lane] + a1 * sW2[lane + 32];
    #pragma unroll
    for (int o = 16; o; o >>= 1) p += __shfl_xor_sync(0xffffffffu, p, o);
    if (lane == 0) {
        out[n] = p + b2[0];
        out[Nn + n] = (float)g_pred[n];
    }
}

// ---------------- launch ----------------
extern "C" void kernel_launch(void* const* d_in, const int* in_sizes, int n_in,
                              void* d_out, int out_size) {
    const int*   node_in  = (const int*)d_in[0];
    const int*   node_out = (const int*)d_in[1];
    const float* ew       = (const float*)d_in[2];
    const int*   hptr     = (const int*)d_in[3];
    const float* qw       = (const float*)d_in[4];
    const float* relW     = (const float*)d_in[5];
    const float* relb     = (const float*)d_in[6];
    const float* linW     = (const float*)d_in[7];
    const float* linb     = (const float*)d_in[8];
    const float* W1       = (const float*)d_in[9];
    const float* b1       = (const float*)d_in[10];
    const float* W2       = (const float*)d_in[11];
    const float* b2       = (const float*)d_in[12];
    float* out = (float*)d_out;

    static bool attr_set = false;
    if (!attr_set) {
        cudaFuncSetAttribute(k_gemm, cudaFuncAttributeMaxDynamicSharedMemorySize, GEMM_SMEM);
        attr_set = true;
    }

    k_init<<<(Nn * Dd + 255) / 256, 256>>>(hptr, qw, relW, relb);
    k_count<<<(Ee + 255) / 256, 256>>>(node_out, ew);
    k_alloc<<<(Nn + 255) / 256, 256>>>();
    k_scatter<<<(Ee + 255) / 256, 256>>>(node_out, node_in, ew);
    k_scale1<<<(Nn + 255) / 256, 256>>>();
    k_agg<0><<<(Nn + 7) / 8, 256>>>(hptr, 0, 0);       // layer 0 aggregation
    k_scale2<<<(Nn + 255) / 256, 256>>>();
    k_buildW<<<(NL * KK * CN + 255) / 256, 256>>>(linW);
    k_gemm<<<(NR / BM), 256, GEMM_SMEM>>>(linb, 0, 1);

    int cur = 1;
    for (int l = 1; l < NL; l++) {
        if (l == NL - 1) {
            k_dot<<<(Nn + 7) / 8, 256>>>(cur, l);
            k_agg<1><<<(Nn + 7) / 8, 256>>>(hptr, cur, l);
        } else {
            k_agg<0><<<(Nn + 7) / 8, 256>>>(hptr, cur, l);
        }
        k_gemm<<<(NR / BM), 256, GEMM_SMEM>>>(linb, l, cur ^ 1);
        cur ^= 1;
    }
    k_final<<<(Nn + 7) / 8, 256>>>(cur, qw, W1, b1, W2, b2, out);
}